// round 5
// baseline (speedup 1.0000x reference)
#include <cuda_runtime.h>
#include <cuda_bf16.h>

#define BB   16
#define CC   192
#define TXN  1024
#define MAXY 4096

// Scratch: token index per output frame (-1 = no token -> z = noise)
__device__ int g_idx[BB * MAXY];

// One block per batch, 1024 threads.
__global__ void build_map_kernel(const float* __restrict__ logw,
                                 const int* __restrict__ x_lengths,
                                 float* __restrict__ y_mask_out) {
    __shared__ int warp_sums[32];
    const int b    = blockIdx.x;
    const int t    = threadIdx.x;
    const int lane = t & 31;
    const int wid  = t >> 5;

    const int xlen = max(x_lengths[b], 1);
    int w = 0;
    if (t < xlen) {
        // accurate expf: feeds ceil(), ulp flips at integer boundaries matter
        w = (int)ceilf(expf(logw[b * TXN + t]));
    }

    // warp-level inclusive scan
    int c = w;
    #pragma unroll
    for (int o = 1; o < 32; o <<= 1) {
        int v = __shfl_up_sync(0xffffffffu, c, o);
        if (lane >= o) c += v;
    }
    if (lane == 31) warp_sums[wid] = c;
    __syncthreads();
    if (wid == 0) {
        int v = warp_sums[lane];
        #pragma unroll
        for (int o = 1; o < 32; o <<= 1) {
            int u = __shfl_up_sync(0xffffffffu, v, o);
            if (lane >= o) v += u;
        }
        warp_sums[lane] = v;
    }
    __syncthreads();

    const int base  = (wid > 0) ? warp_sums[wid - 1] : 0;
    const int cum   = base + c;               // inclusive prefix sum
    const int total = warp_sums[31];
    const int ylen  = min(max(total, 1), MAXY);

    int* __restrict__ row = g_idx + b * MAXY;

    // band scatter: frames [cum-w, cum) belong to token t
    const int end = min(cum, MAXY);
    for (int ty = cum - w; ty < end; ty++) row[ty] = t;

    // tail fill: frames beyond total have no token
    const int tail0 = min(total, MAXY);
    for (int ty = tail0 + t; ty < MAXY; ty += TXN) row[ty] = -1;

    // y_mask, one float4 per thread
    if (y_mask_out != nullptr) {
        const int v0 = t * 4;
        float4 m;
        m.x = (v0 + 0 < ylen) ? 1.0f : 0.0f;
        m.y = (v0 + 1 < ylen) ? 1.0f : 0.0f;
        m.z = (v0 + 2 < ylen) ? 1.0f : 0.0f;
        m.w = (v0 + 3 < ylen) ? 1.0f : 0.0f;
        reinterpret_cast<float4*>(y_mask_out + b * MAXY)[t] = m;
    }
}

// One block per (b,c) row, 256 threads x 4 float4 = 4096 ty.
// Stage m and PRE-EXPONENTIATED logs into smem (coalesced), then a short
// LDS -> FFMA -> STG loop. Registers kept minimal (loads live per-iteration)
// and occupancy forced to 8 blocks/SM so warps hide the latency.
__global__ void __launch_bounds__(256, 8)
expand_kernel(const float* __restrict__ m_p,
              const float* __restrict__ logs_p,
              const float* __restrict__ noise,
              float* __restrict__ z) {
    __shared__ float sm[TXN];
    __shared__ float se[TXN];

    const int bc  = blockIdx.x;      // 0..BB*CC-1
    const int b   = bc / CC;
    const int tid = threadIdx.x;

    const float4* __restrict__ nz4 = reinterpret_cast<const float4*>(noise) + (size_t)bc * (MAXY / 4);
    float4*       __restrict__ z4  = reinterpret_cast<float4*>(z)           + (size_t)bc * (MAXY / 4);
    const int4*   __restrict__ ix4 = reinterpret_cast<const int4*>(g_idx)   + b * (MAXY / 4);

    // ---- stage: m as-is, logs pre-exponentiated (MUFU off the hot chain) ----
    {
        float4 mv = reinterpret_cast<const float4*>(m_p    + (size_t)bc * TXN)[tid];
        float4 sv = reinterpret_cast<const float4*>(logs_p + (size_t)bc * TXN)[tid];
        reinterpret_cast<float4*>(sm)[tid] = mv;
        float4 e;
        e.x = __expf(sv.x); e.y = __expf(sv.y);
        e.z = __expf(sv.z); e.w = __expf(sv.w);
        reinterpret_cast<float4*>(se)[tid] = e;
    }
    __syncthreads();

    // ---- stream: per-iteration loads die quickly; warps supply the MLP ----
    #pragma unroll
    for (int j = 0; j < 4; j++) {
        const int   v  = tid + j * 256;
        const float4 n = __ldcs(&nz4[v]);
        const int4  ix = ix4[v];
        float4 o;
        o.x = (ix.x >= 0) ? fmaf(n.x, se[ix.x], sm[ix.x]) : n.x;
        o.y = (ix.y >= 0) ? fmaf(n.y, se[ix.y], sm[ix.y]) : n.y;
        o.z = (ix.z >= 0) ? fmaf(n.z, se[ix.z], sm[ix.z]) : n.z;
        o.w = (ix.w >= 0) ? fmaf(n.w, se[ix.w], sm[ix.w]) : n.w;
        __stcs(&z4[v], o);
    }
}

extern "C" void kernel_launch(void* const* d_in, const int* in_sizes, int n_in,
                              void* d_out, int out_size) {
    const float* m_p    = (const float*)d_in[0];
    const float* logs_p = (const float*)d_in[1];
    const float* logw   = (const float*)d_in[2];
    const float* noise  = (const float*)d_in[3];
    const int*   xlens  = (const int*)d_in[4];

    float* out = (float*)d_out;
    const int zsize = BB * CC * MAXY;            // 12,582,912
    float* z = out;
    float* y_mask = (out_size >= zsize + BB * MAXY) ? (out + zsize) : nullptr;

    build_map_kernel<<<BB, TXN>>>(logw, xlens, y_mask);
    expand_kernel<<<BB * CC, 256>>>(m_p, logs_p, noise, z);
}